// round 14
// baseline (speedup 1.0000x reference)
#include <cuda_runtime.h>
#include <cuda_fp16.h>
#include <cstdint>

// ---------------------------------------------------------------------------
// cross_set_score (v10): v9 + ldmatrix.x4 B fragments (standard slot
// convention for A to match), unroll-2 score mainloop, tiled prep transpose.
//  K0: g_W1h = transpose(W1) fp16 (SMEM-tiled); zero completion counter
//  K1: proj: CTA = 128 x-rows (reg-resident fp16) x 8 heads; W1 dbl-buffered
//  K2: score: CTA = (pair, head): A reg-resident from gmem, full B in SMEM;
//      branch-free leaky (0.65v+0.35|v|); last CTA finalizes output
// ---------------------------------------------------------------------------

#define NSET  16
#define MITEM 256
#define DIN   128
#define NHEAD 8
#define DHEAD 64
#define NPAIR 136

#define W1STR 72       // words (fp16x2); ==8 mod 32
#define BSTR  40       // words (fp16x2); ==8 mod 32

#define SCORE_GRID (NPAIR * NHEAD)

__device__ __half g_H[NSET * NSET * NHEAD * MITEM * DHEAD];  // 67 MB scratch
__device__ __half g_W1h[NHEAD * DHEAD * DIN];                // [head][e][d]
__device__ float  g_scratch[NPAIR * NHEAD];
__device__ int    g_count;

// ---------------- helpers ----------------
__device__ __forceinline__ uint32_t packh2(float a, float b) {
    __half2 h = __floats2half2_rn(a, b);
    return *(uint32_t*)&h;
}
__device__ __forceinline__ void mma_f16(float* c, const uint32_t* a, const uint32_t* b) {
    asm volatile(
        "mma.sync.aligned.m16n8k16.row.col.f32.f16.f16.f32 "
        "{%0,%1,%2,%3}, {%4,%5,%6,%7}, {%8,%9}, {%0,%1,%2,%3};"
        : "+f"(c[0]), "+f"(c[1]), "+f"(c[2]), "+f"(c[3])
        : "r"(a[0]), "r"(a[1]), "r"(a[2]), "r"(a[3]), "r"(b[0]), "r"(b[1]));
}
__device__ __forceinline__ void ldsm_x4(uint32_t* r, uint32_t addr) {
    asm volatile("ldmatrix.sync.aligned.m8n8.x4.shared.b16 {%0,%1,%2,%3}, [%4];"
                 : "=r"(r[0]), "=r"(r[1]), "=r"(r[2]), "=r"(r[3]) : "r"(addr));
}
__device__ __forceinline__ void cp_async16(uint32_t smem_addr, const void* gptr) {
    asm volatile("cp.async.cg.shared.global [%0], [%1], 16;"
                 :: "r"(smem_addr), "l"(gptr) : "memory");
}
__device__ __forceinline__ void cp_commit() {
    asm volatile("cp.async.commit_group;" ::: "memory");
}
__device__ __forceinline__ void cp_wait0() {
    asm volatile("cp.async.wait_group 0;" ::: "memory");
}
__device__ __forceinline__ uint32_t smem_u32(const void* p) {
    return (uint32_t)__cvta_generic_to_shared(p);
}

// ============================================================================
// Kernel 0: tiled transpose + fp16-round W1; reset counter.
// grid 64 (16 he-tiles x 4 d-tiles), block (32,8).
// ============================================================================
__global__ void prep_w1(const float* __restrict__ W1)
{
    __shared__ float t[32][33];
    const int bhe = (blockIdx.x & 15) * 32;
    const int bd  = (blockIdx.x >> 4) * 32;
    const int tx  = threadIdx.x, ty = threadIdx.y;
    if (blockIdx.x == 0 && tx == 0 && ty == 0) g_count = 0;
    #pragma unroll
    for (int k = 0; k < 4; ++k)    // read W1[d][he], coalesced in tx (he)
        t[ty + 8 * k][tx] = W1[(bd + ty + 8 * k) * (NHEAD * DHEAD) + bhe + tx];
    __syncthreads();
    #pragma unroll
    for (int k = 0; k < 4; ++k)    // write g_W1h[he][d], coalesced in tx (d)
        g_W1h[(size_t)(bhe + ty + 8 * k) * DIN + bd + tx] =
            __float2half(t[tx][ty + 8 * k]);
}

// ============================================================================
// Kernel 1: projection. grid = 512 CTAs (256 tiles x 2 halves), 256 thr.
// A resident (standard slots); W1 B-fragments via ldmatrix.x4.
// ============================================================================
__global__ __launch_bounds__(256, 3)
void proj_kernel(const float* __restrict__ x)
{
    extern __shared__ uint32_t w1s[];    // 2 slots of [64][W1STR]

    const int bx   = blockIdx.x;
    const int tile = bx >> 1;
    const int rh   = bx & 1;
    const int tid  = threadIdx.x;
    const int wid  = tid >> 5;
    const int lane = tid & 31;
    const int r    = lane >> 2;
    const int c    = lane & 3;
    const uint32_t slot_bytes = DHEAD * W1STR * 4;
    const uint32_t w1s_base   = smem_u32(w1s);

    auto stage_head = [&](int h, int s) {
        const char* src = (const char*)(g_W1h + (size_t)h * DHEAD * DIN);
        const uint32_t dstb = w1s_base + s * slot_bytes;
        #pragma unroll
        for (int it = 0; it < 4; ++it) {
            int idx = tid + it * 256;
            int e = idx >> 4, dq = idx & 15;
            cp_async16(dstb + (e * W1STR + dq * 4) * 4, src + idx * 16);
        }
        cp_commit();
    };

    stage_head(0, 0);

    // ---- A resident, STANDARD slots: a0=k{2c,2c+1}@r, a1=same@r+8,
    //      a2=k{8+2c,+1}@r, a3=same@r+8 ----
    uint32_t aF[8][4];
    {
        const float* xr0 = x + (size_t)(tile * MITEM + rh * 128 + wid * 16 + r) * DIN;
        const float* xr8 = xr0 + 8 * DIN;
        #pragma unroll
        for (int ks = 0; ks < 8; ++ks) {
            float2 p0 = *(const float2*)(xr0 + ks * 16 + 2 * c);
            float2 p1 = *(const float2*)(xr0 + ks * 16 + 8 + 2 * c);
            float2 q0 = *(const float2*)(xr8 + ks * 16 + 2 * c);
            float2 q1 = *(const float2*)(xr8 + ks * 16 + 8 + 2 * c);
            aF[ks][0] = packh2(p0.x, p0.y);
            aF[ks][1] = packh2(q0.x, q0.y);
            aF[ks][2] = packh2(p1.x, p1.y);
            aF[ks][3] = packh2(q1.x, q1.y);
        }
    }

    cp_wait0();
    __syncthreads();

    // ldmatrix lane addressing for W1 B tiles:
    // lanes 0-7: (n0 rows, lo words), 8-15: (n0, hi), 16-23: (n1, lo), 24-31: (n1, hi)
    const int lrow = (lane & 7) + ((lane >> 4) * 8);     // row within 16-row ntp block
    const int lcol = ((lane >> 3) & 1) * 4;              // word-col offset 0 or 4

    #pragma unroll 1
    for (int h = 0; h < NHEAD; ++h) {
        const int s = h & 1;
        if (h < NHEAD - 1) stage_head(h + 1, s ^ 1);

        const uint32_t w1cb = w1s_base + s * slot_bytes;
        uint2* Hw = (uint2*)(g_H + ((size_t)(tile * NHEAD + h) * MITEM
                                    + rh * 128 + wid * 16) * DHEAD);

        #pragma unroll
        for (int ntp = 0; ntp < 4; ++ntp) {
            const int n0 = ntp * 16;
            // lane address for this ntp block (row n0+lrow), word-col lcol
            uint32_t lb = w1cb + (((n0 + lrow) * W1STR) + lcol) * 4;
            float acc0[4] = {0.f, 0.f, 0.f, 0.f};
            float acc1[4] = {0.f, 0.f, 0.f, 0.f};
            #pragma unroll
            for (int ks = 0; ks < 8; ++ks) {
                uint32_t bf[4];     // R0=b0(n0),R1=b1(n0),R2=b0(n1),R3=b1(n1)
                ldsm_x4(bf, lb + ks * 32);
                mma_f16(acc0, aF[ks], bf + 0);
                mma_f16(acc1, aF[ks], bf + 2);
            }
            // packed store (unchanged: output layout independent of input slots)
            uint2 lo = { packh2(acc0[0], acc0[1]), packh2(acc1[0], acc1[1]) };
            uint2 hi = { packh2(acc0[2], acc0[3]), packh2(acc1[2], acc1[3]) };
            Hw[(size_t)r * 16 + ntp * 4 + c]       = lo;
            Hw[(size_t)(r + 8) * 16 + ntp * 4 + c] = hi;
        }

        if (h < NHEAD - 1) {
            cp_wait0();
            __syncthreads();
        }
    }
}

// ============================================================================
// Kernel 2: score. grid = 1088 CTAs, 256 threads.
// A resident from gmem (standard slots), B via ldmatrix.x4 from SMEM.
// ============================================================================
__global__ __launch_bounds__(256, 3)
void score_kernel(const float* __restrict__ nItem,
                  const float* __restrict__ W2,
                  float* __restrict__ out)
{
    extern __shared__ uint32_t sm2[];
    uint32_t* Bs   = sm2;                              // [256][BSTR]
    float*    red  = (float*)(sm2 + 256 * BSTR);       // [8]
    int*      flag = (int*)(red + 8);

    const int bx   = blockIdx.x;
    const int pair = bx >> 3;
    const int head = bx & 7;
    const int tid  = threadIdx.x;
    const int wid  = tid >> 5;
    const int lane = tid & 31;
    const int r    = lane >> 2;
    const int c    = lane & 3;

    // pair -> (ii <= jj)
    int q = pair, jj = 0;
    while (q >= jj + 1) { q -= (jj + 1); ++jj; }
    const int ii = q;

    const __half* HA = g_H + (size_t)((jj * NSET + ii) * NHEAD + head) * MITEM * DHEAD;
    const __half* HB = g_H + (size_t)((ii * NSET + jj) * NHEAD + head) * MITEM * DHEAD;

    // ---- kick off B staging (2048 uint4 = 32KB) ----
    {
        const uint32_t bs_base = smem_u32(Bs);
        const char* src = (const char*)HB;
        #pragma unroll
        for (int it = 0; it < 8; ++it) {
            int idx = tid + it * 256;
            int row = idx >> 3, cq = idx & 7;
            cp_async16(bs_base + (row * BSTR + cq * 4) * 4, src + idx * 16);
        }
        cp_commit();
    }

    // ---- A resident, STANDARD slots: words {ks*8+c} and {ks*8+4+c} ----
    uint32_t aF[2][4][4];
    {
        const uint32_t* HAw = (const uint32_t*)HA;     // 32 words/row
        const int wm = wid * 32;
        #pragma unroll
        for (int mt = 0; mt < 2; ++mt) {
            const uint32_t* a0 = HAw + (size_t)(wm + mt * 16 + r) * 32;
            const uint32_t* a8 = a0 + 8 * 32;
            #pragma unroll
            for (int ks = 0; ks < 4; ++ks) {
                aF[mt][ks][0] = a0[ks * 8 + c];
                aF[mt][ks][1] = a8[ks * 8 + c];
                aF[mt][ks][2] = a0[ks * 8 + 4 + c];
                aF[mt][ks][3] = a8[ks * 8 + 4 + c];
            }
        }
    }

    cp_wait0();
    __syncthreads();

    // ldmatrix lane addressing: lane l -> row (l&7), word-col 4*(l>>3)
    // (tiles: 4 consecutive word-col groups of the same 8 rows)
    uint32_t lb = smem_u32(Bs) + (((lane & 7) * BSTR) + (lane >> 3) * 4) * 4;

    // ---- mainloop: 32 n-tiles; 2 LDSM.x4 + 8 mma + 8 FADD per nt ----
    float s1 = 0.f, s2 = 0.f;
    #pragma unroll 2
    for (int nt = 0; nt < 32; ++nt) {
        uint32_t b01[4], b23[4];
        ldsm_x4(b01, lb);            // ks0: {b01[0],b01[1]}, ks1: {b01[2],b01[3]}
        ldsm_x4(b23, lb + 16 * 4);   // ks2, ks3
        lb += 8 * BSTR * 4;
        float acc0[4] = {0.f, 0.f, 0.f, 0.f};
        float acc1[4] = {0.f, 0.f, 0.f, 0.f};
        mma_f16(acc0, aF[0][0], b01 + 0);  mma_f16(acc1, aF[1][0], b01 + 0);
        mma_f16(acc0, aF[0][1], b01 + 2);  mma_f16(acc1, aF[1][1], b01 + 2);
        mma_f16(acc0, aF[0][2], b23 + 0);  mma_f16(acc1, aF[1][2], b23 + 0);
        mma_f16(acc0, aF[0][3], b23 + 2);  mma_f16(acc1, aF[1][3], b23 + 2);
        #pragma unroll
        for (int e = 0; e < 4; ++e) {
            s1 += acc0[e];          s2 += fabsf(acc0[e]);
            s1 += acc1[e];          s2 += fabsf(acc1[e]);
        }
    }
    float sum = 0.65f * s1 + 0.35f * s2;   // == sum leaky(v), alpha=0.3

    // ---- CTA reduce ----
    #pragma unroll
    for (int off = 16; off; off >>= 1)
        sum += __shfl_xor_sync(0xffffffffu, sum, off);
    if (lane == 0) red[wid] = sum;
    __syncthreads();
    if (tid == 0) {
        float t = 0.f;
        #pragma unroll
        for (int w = 0; w < 8; ++w) t += red[w];
        g_scratch[pair * NHEAD + head] = t;
        __threadfence();
        int done = atomicAdd(&g_count, 1);
        *flag = (done == SCORE_GRID - 1);
    }
    __syncthreads();

    // ---- last CTA: finalize ----
    if (*flag) {
        __threadfence();
        const int t = tid;             // t = j*16 + i
        const int j = t >> 4, i = t & 15;
        const int a = (j > i) ? j : i;
        const int b = (j > i) ? i : j;
        const int p = a * (a + 1) / 2 + b;
        float s = 0.f;
        #pragma unroll
        for (int hh = 0; hh < NHEAD; ++hh)
            s += g_scratch[p * NHEAD + hh] * W2[hh];
        out[t] = s / (8.0f * nItem[i] * nItem[j]);   // 8 = sqrt(D=64)
    }
}

// ---------------- entry point ----------------
#define SMEM_K1 (2 * DHEAD * W1STR * 4)          // 36864
#define SMEM_K2 (256 * BSTR * 4 + 64)            // 41024

extern "C" void kernel_launch(void* const* d_in, const int* in_sizes, int n_in,
                              void* d_out, int out_size)
{
    const float* x = nullptr;
    const float* nItem = nullptr;
    const float* W1 = nullptr;
    const float* W2 = nullptr;
    for (int k = 0; k < n_in; ++k) {
        switch (in_sizes[k]) {
            case NSET * NSET * MITEM * DIN: x     = (const float*)d_in[k]; break;
            case NSET:                      nItem = (const float*)d_in[k]; break;
            case DIN * NHEAD * DHEAD:       W1    = (const float*)d_in[k]; break;
            case NHEAD:                     W2    = (const float*)d_in[k]; break;
        }
    }

    static bool attr_done = false;
    if (!attr_done) {
        cudaFuncSetAttribute(proj_kernel,
                             cudaFuncAttributeMaxDynamicSharedMemorySize, SMEM_K1);
        cudaFuncSetAttribute(score_kernel,
                             cudaFuncAttributeMaxDynamicSharedMemorySize, SMEM_K2);
        attr_done = true;
    }

    prep_w1<<<64, dim3(32, 8)>>>(W1);
    proj_kernel<<<NSET * NSET * 2, 256, SMEM_K1>>>(x);
    score_kernel<<<SCORE_GRID, 256, SMEM_K2>>>(nItem, W2, (float*)d_out);
}

// round 15
// speedup vs baseline: 1.3719x; 1.3719x over previous
#include <cuda_runtime.h>
#include <cuda_fp16.h>
#include <cstdint>

// ---------------------------------------------------------------------------
// cross_set_score (v11): v9 score/prep verbatim; proj widened to 32 rows/warp
// (CTA = full 256-row tile, grid 256): each W1 fragment pair feeds 4 mmas,
// halving W1 LDS bytes per mma and halving W1 staging traffic.
//  K0: g_W1h = transpose(W1) fp16; zero completion counter
//  K1: proj: CTA = 256 x-rows (reg-resident fp16, 32/warp) x 8 heads
//  K2: score: CTA = (pair, head): A reg-resident from gmem, full B in SMEM;
//      branch-free leaky (0.65v+0.35|v|); last CTA finalizes output
// ---------------------------------------------------------------------------

#define NSET  16
#define MITEM 256
#define DIN   128
#define NHEAD 8
#define DHEAD 64
#define NPAIR 136

#define W1STR 72       // words (fp16x2); ==8 mod 32 -> conflict-free LDS.64
#define BSTR  40       // words (fp16x2); ==8 mod 32 -> conflict-free LDS.64

#define SCORE_GRID (NPAIR * NHEAD)

__device__ __half g_H[NSET * NSET * NHEAD * MITEM * DHEAD];  // 67 MB scratch
__device__ __half g_W1h[NHEAD * DHEAD * DIN];                // [head][e][d]
__device__ float  g_scratch[NPAIR * NHEAD];
__device__ int    g_count;

// ---------------- helpers ----------------
__device__ __forceinline__ uint32_t packh2(float a, float b) {
    __half2 h = __floats2half2_rn(a, b);
    return *(uint32_t*)&h;
}
__device__ __forceinline__ void mma_f16(float* c, const uint32_t* a, const uint32_t* b) {
    asm volatile(
        "mma.sync.aligned.m16n8k16.row.col.f32.f16.f16.f32 "
        "{%0,%1,%2,%3}, {%4,%5,%6,%7}, {%8,%9}, {%0,%1,%2,%3};"
        : "+f"(c[0]), "+f"(c[1]), "+f"(c[2]), "+f"(c[3])
        : "r"(a[0]), "r"(a[1]), "r"(a[2]), "r"(a[3]), "r"(b[0]), "r"(b[1]));
}
__device__ __forceinline__ void cp_async16(uint32_t smem_addr, const void* gptr) {
    asm volatile("cp.async.cg.shared.global [%0], [%1], 16;"
                 :: "r"(smem_addr), "l"(gptr) : "memory");
}
__device__ __forceinline__ void cp_commit() {
    asm volatile("cp.async.commit_group;" ::: "memory");
}
__device__ __forceinline__ void cp_wait0() {
    asm volatile("cp.async.wait_group 0;" ::: "memory");
}
__device__ __forceinline__ uint32_t smem_u32(const void* p) {
    return (uint32_t)__cvta_generic_to_shared(p);
}

// ============================================================================
// Kernel 0: transpose + fp16-round W1; reset completion counter.
// ============================================================================
__global__ void prep_w1(const float* __restrict__ W1)
{
    const int idx = blockIdx.x * 1024 + threadIdx.x;   // 65536 total
    if (idx == 0) g_count = 0;
    const int he  = idx >> 7;            // head*64 + e
    const int d   = idx & 127;
    g_W1h[idx] = __float2half(W1[d * (NHEAD * DHEAD) + he]);
}

// ============================================================================
// Kernel 1: projection. grid = 256 CTAs (one full tile each), 256 thr.
// Warp owns 32 x-rows resident (fp16, 64 regs) across all 8 heads.
// W1 double-buffered via cp.async; each (b0,b1) pair feeds 4 mmas.
// ============================================================================
__global__ __launch_bounds__(256, 2)
void proj_kernel(const float* __restrict__ x)
{
    extern __shared__ uint32_t w1s[];    // 2 slots of [64][W1STR]

    const int tile = blockIdx.x;
    const int tid  = threadIdx.x;
    const int wid  = tid >> 5;
    const int lane = tid & 31;
    const int r    = lane >> 2;
    const int c    = lane & 3;
    const uint32_t slot_bytes = DHEAD * W1STR * 4;
    const uint32_t w1s_base   = smem_u32(w1s);

    auto stage_head = [&](int h, int s) {
        const char* src = (const char*)(g_W1h + (size_t)h * DHEAD * DIN);
        const uint32_t dstb = w1s_base + s * slot_bytes;
        #pragma unroll
        for (int it = 0; it < 4; ++it) {
            int idx = tid + it * 256;
            int e = idx >> 4, dq = idx & 15;
            cp_async16(dstb + (e * W1STR + dq * 4) * 4, src + idx * 16);
        }
        cp_commit();
    };

    stage_head(0, 0);

    // ---- A resident: 32 rows (2 m-tiles) x 128 K per warp ----
    uint32_t aF[2][8][4];
    #pragma unroll
    for (int mt = 0; mt < 2; ++mt) {
        const float* xr0 = x + (size_t)(tile * MITEM + wid * 32 + mt * 16 + r) * DIN;
        const float* xr8 = xr0 + 8 * DIN;
        #pragma unroll
        for (int ks = 0; ks < 8; ++ks) {
            float4 v0 = *(const float4*)(xr0 + ks * 16 + 4 * c);
            float4 v8 = *(const float4*)(xr8 + ks * 16 + 4 * c);
            aF[mt][ks][0] = packh2(v0.x, v0.y);
            aF[mt][ks][2] = packh2(v0.z, v0.w);
            aF[mt][ks][1] = packh2(v8.x, v8.y);
            aF[mt][ks][3] = packh2(v8.z, v8.w);
        }
    }

    cp_wait0();
    __syncthreads();

    #pragma unroll 1
    for (int h = 0; h < NHEAD; ++h) {
        const int s = h & 1;
        if (h < NHEAD - 1) stage_head(h + 1, s ^ 1);

        const uint32_t* w1c = w1s + s * (DHEAD * W1STR);
        uint2* Hw = (uint2*)(g_H + ((size_t)(tile * NHEAD + h) * MITEM
                                    + wid * 32) * DHEAD);

        #pragma unroll
        for (int ntp = 0; ntp < 4; ++ntp) {
            const int n0 = ntp * 16;
            const int n1 = n0 + 8;
            float acc[2][2][4];
            #pragma unroll
            for (int mt = 0; mt < 2; ++mt)
                #pragma unroll
                for (int n = 0; n < 2; ++n)
                    #pragma unroll
                    for (int e = 0; e < 4; ++e) acc[mt][n][e] = 0.f;

            #pragma unroll
            for (int ks = 0; ks < 8; ++ks) {
                uint2 b0 = *(const uint2*)&w1c[(n0 + r) * W1STR + ks * 8 + 2 * c];
                uint2 b1 = *(const uint2*)&w1c[(n1 + r) * W1STR + ks * 8 + 2 * c];
                mma_f16(acc[0][0], aF[0][ks], (const uint32_t*)&b0);
                mma_f16(acc[0][1], aF[0][ks], (const uint32_t*)&b1);
                mma_f16(acc[1][0], aF[1][ks], (const uint32_t*)&b0);
                mma_f16(acc[1][1], aF[1][ks], (const uint32_t*)&b1);
            }
            // packed store per m-tile (same K-perm convention as v9)
            #pragma unroll
            for (int mt = 0; mt < 2; ++mt) {
                uint2 lo = { packh2(acc[mt][0][0], acc[mt][0][1]),
                             packh2(acc[mt][1][0], acc[mt][1][1]) };
                uint2 hi = { packh2(acc[mt][0][2], acc[mt][0][3]),
                             packh2(acc[mt][1][2], acc[mt][1][3]) };
                Hw[(size_t)(mt * 16 + r) * 16 + ntp * 4 + c]     = lo;
                Hw[(size_t)(mt * 16 + r + 8) * 16 + ntp * 4 + c] = hi;
            }
        }

        if (h < NHEAD - 1) {
            cp_wait0();
            __syncthreads();
        }
    }
}

// ============================================================================
// Kernel 2: score (v9 verbatim). grid = 1088 CTAs, 256 threads.
// ============================================================================
__global__ __launch_bounds__(256, 3)
void score_kernel(const float* __restrict__ nItem,
                  const float* __restrict__ W2,
                  float* __restrict__ out)
{
    extern __shared__ uint32_t sm2[];
    uint32_t* Bs   = sm2;                              // [256][BSTR]
    float*    red  = (float*)(sm2 + 256 * BSTR);       // [8]
    int*      flag = (int*)(red + 8);

    const int bx   = blockIdx.x;
    const int pair = bx >> 3;
    const int head = bx & 7;
    const int tid  = threadIdx.x;
    const int wid  = tid >> 5;
    const int lane = tid & 31;
    const int r    = lane >> 2;
    const int c    = lane & 3;

    // pair -> (ii <= jj)
    int q = pair, jj = 0;
    while (q >= jj + 1) { q -= (jj + 1); ++jj; }
    const int ii = q;

    const __half* HA = g_H + (size_t)((jj * NSET + ii) * NHEAD + head) * MITEM * DHEAD;
    const __half* HB = g_H + (size_t)((ii * NSET + jj) * NHEAD + head) * MITEM * DHEAD;

    // ---- kick off B staging (2048 uint4 = 32KB), then load A ----
    {
        const uint32_t bs_base = smem_u32(Bs);
        const char* src = (const char*)HB;
        #pragma unroll
        for (int it = 0; it < 8; ++it) {
            int idx = tid + it * 256;
            int row = idx >> 3, cq = idx & 7;          // 8 uint4 per row
            cp_async16(bs_base + (row * BSTR + cq * 4) * 4, src + idx * 16);
        }
        cp_commit();
    }

    // A resident: 32 rows (2 m-tiles) x 64 K per warp (4 k16-steps x 4 regs)
    uint32_t aF[2][4][4];
    {
        const uint32_t* HAw = (const uint32_t*)HA;     // fp16x2 words, 32/row
        const int wm = wid * 32;
        #pragma unroll
        for (int mt = 0; mt < 2; ++mt) {
            const uint32_t* a0 = HAw + (size_t)(wm + mt * 16 + r) * 32;
            const uint32_t* a8 = a0 + 8 * 32;
            #pragma unroll
            for (int ks = 0; ks < 4; ++ks) {
                uint2 lo = *(const uint2*)(a0 + ks * 8 + 2 * c);
                uint2 hi = *(const uint2*)(a8 + ks * 8 + 2 * c);
                aF[mt][ks][0] = lo.x; aF[mt][ks][2] = lo.y;
                aF[mt][ks][1] = hi.x; aF[mt][ks][3] = hi.y;
            }
        }
    }

    cp_wait0();
    __syncthreads();

    // ---- mainloop: 32 n-tiles; dual accumulators (branch-free leaky) ----
    float s1 = 0.f, s2 = 0.f;
    #pragma unroll 1
    for (int nt = 0; nt < 32; ++nt) {
        float acc0[4] = {0.f, 0.f, 0.f, 0.f};
        float acc1[4] = {0.f, 0.f, 0.f, 0.f};
        #pragma unroll
        for (int ks = 0; ks < 4; ++ks) {
            uint2 b = *(const uint2*)&Bs[(nt * 8 + r) * BSTR + ks * 8 + 2 * c];
            mma_f16(acc0, aF[0][ks], (const uint32_t*)&b);
            mma_f16(acc1, aF[1][ks], (const uint32_t*)&b);
        }
        #pragma unroll
        for (int e = 0; e < 4; ++e) {
            s1 += acc0[e];          s2 += fabsf(acc0[e]);
            s1 += acc1[e];          s2 += fabsf(acc1[e]);
        }
    }
    float sum = 0.65f * s1 + 0.35f * s2;   // == sum of leaky(v), alpha=0.3

    // ---- CTA reduce ----
    #pragma unroll
    for (int off = 16; off; off >>= 1)
        sum += __shfl_xor_sync(0xffffffffu, sum, off);
    if (lane == 0) red[wid] = sum;
    __syncthreads();
    if (tid == 0) {
        float t = 0.f;
        #pragma unroll
        for (int w = 0; w < 8; ++w) t += red[w];
        g_scratch[pair * NHEAD + head] = t;
        __threadfence();
        int done = atomicAdd(&g_count, 1);
        *flag = (done == SCORE_GRID - 1);
    }
    __syncthreads();

    // ---- last CTA: finalize ----
    if (*flag) {
        __threadfence();
        const int t = tid;             // t = j*16 + i
        const int j = t >> 4, i = t & 15;
        const int a = (j > i) ? j : i;
        const int b = (j > i) ? i : j;
        const int p = a * (a + 1) / 2 + b;
        float s = 0.f;
        #pragma unroll
        for (int hh = 0; hh < NHEAD; ++hh)
            s += g_scratch[p * NHEAD + hh] * W2[hh];
        out[t] = s / (8.0f * nItem[i] * nItem[j]);   // 8 = sqrt(D=64)
    }
}

// ---------------- entry point ----------------
#define SMEM_K1 (2 * DHEAD * W1STR * 4)          // 36864
#define SMEM_K2 (256 * BSTR * 4 + 64)            // 41024

extern "C" void kernel_launch(void* const* d_in, const int* in_sizes, int n_in,
                              void* d_out, int out_size)
{
    const float* x = nullptr;
    const float* nItem = nullptr;
    const float* W1 = nullptr;
    const float* W2 = nullptr;
    for (int k = 0; k < n_in; ++k) {
        switch (in_sizes[k]) {
            case NSET * NSET * MITEM * DIN: x     = (const float*)d_in[k]; break;
            case NSET:                      nItem = (const float*)d_in[k]; break;
            case DIN * NHEAD * DHEAD:       W1    = (const float*)d_in[k]; break;
            case NHEAD:                     W2    = (const float*)d_in[k]; break;
        }
    }

    static bool attr_done = false;
    if (!attr_done) {
        cudaFuncSetAttribute(proj_kernel,
                             cudaFuncAttributeMaxDynamicSharedMemorySize, SMEM_K1);
        cudaFuncSetAttribute(score_kernel,
                             cudaFuncAttributeMaxDynamicSharedMemorySize, SMEM_K2);
        attr_done = true;
    }

    prep_w1<<<64, 1024>>>(W1);
    proj_kernel<<<NSET * NSET, 256, SMEM_K1>>>(x);
    score_kernel<<<SCORE_GRID, 256, SMEM_K2>>>(nItem, W2, (float*)d_out);
}

// round 16
// speedup vs baseline: 1.5273x; 1.1133x over previous
#include <cuda_runtime.h>
#include <cuda_fp16.h>
#include <cstdint>

// ---------------------------------------------------------------------------
// cross_set_score (v12): FULLY FUSED. One CTA per unordered pair (grid 136).
// Each CTA, per head h:
//   1. HA = xA @ W1_h  (mma; acc maps DIRECTLY to score A-operand regs)
//   2. HB = xB @ W1_h  (mma; acc packed to SMEM as score B operand)
//   3. S += W2[h] * sum leakyrelu(HA @ HB^T)   (branch-free 0.65v+0.35|v|)
// x tiles staged once (fp16, SMEM), W1 single-buffered with cp.async
// prefetch overlapping the score phase. H never touches global memory.
// No atomics, no scratch, no finalize kernel.
// Fragment conventions (verified consistent):
//   proj: A=x, B=W1 both straight SMEM; slot pair (a0,a2)/(b0,b1) <- adjacent
//         words ks*8+2c (k-halves {16ks+4c..}) - shared permutation.
//   score: aF[mt][k] from proj acc: a0=pack(acc[2k][0,1]), a1=pack(acc[2k][2,3]),
//         a2=pack(acc[2k+1][0,1]), a3=pack(acc[2k+1][2,3])  (cols 16k+2c / +8+2c)
//         Bs word (row*40 + k*8+2c) = cols{16k+2c,+1}, word+1 = {16k+8+2c,+1}.
// ---------------------------------------------------------------------------

#define NSET  16
#define MITEM 256
#define DIN   128
#define NHEAD 8
#define DHEAD 64
#define NPAIR 136

#define XSTR  72       // x/W1 SMEM stride in 32-bit words (64 + 8 pad)
#define BSTR  40       // H_B SMEM stride (32 + 8 pad)

// SMEM word offsets
#define OFF_XA  0
#define OFF_XB  (256 * XSTR)                 // 18432
#define OFF_W1  (2 * 256 * XSTR)             // 36864
#define OFF_BS  (OFF_W1 + 64 * XSTR)         // 41472
#define OFF_RED (OFF_BS + 256 * BSTR)        // 51712
#define SMEM_WORDS (OFF_RED + 16)
#define SMEM_BYTES (SMEM_WORDS * 4)          // ~206,912 B

__device__ __half g_W1h[NHEAD * DHEAD * DIN];   // [head][e][d], fp16

// ---------------- helpers ----------------
__device__ __forceinline__ uint32_t packh2(float a, float b) {
    __half2 h = __floats2half2_rn(a, b);
    return *(uint32_t*)&h;
}
__device__ __forceinline__ void mma_f16(float* c, const uint32_t* a, const uint32_t* b) {
    asm volatile(
        "mma.sync.aligned.m16n8k16.row.col.f32.f16.f16.f32 "
        "{%0,%1,%2,%3}, {%4,%5,%6,%7}, {%8,%9}, {%0,%1,%2,%3};"
        : "+f"(c[0]), "+f"(c[1]), "+f"(c[2]), "+f"(c[3])
        : "r"(a[0]), "r"(a[1]), "r"(a[2]), "r"(a[3]), "r"(b[0]), "r"(b[1]));
}
__device__ __forceinline__ void cp_async16(uint32_t smem_addr, const void* gptr) {
    asm volatile("cp.async.cg.shared.global [%0], [%1], 16;"
                 :: "r"(smem_addr), "l"(gptr) : "memory");
}
__device__ __forceinline__ void cp_commit() {
    asm volatile("cp.async.commit_group;" ::: "memory");
}
__device__ __forceinline__ void cp_wait0() {
    asm volatile("cp.async.wait_group 0;" ::: "memory");
}
__device__ __forceinline__ uint32_t smem_u32(const void* p) {
    return (uint32_t)__cvta_generic_to_shared(p);
}

// ============================================================================
// Kernel 0: transpose + fp16-round W1 -> g_W1h[head][e][d].
// ============================================================================
__global__ void prep_w1(const float* __restrict__ W1)
{
    const int idx = blockIdx.x * 1024 + threadIdx.x;   // 65536 total
    const int he  = idx >> 7;            // head*64 + e
    const int d   = idx & 127;
    g_W1h[idx] = __float2half(W1[d * (NHEAD * DHEAD) + he]);
}

// ============================================================================
// Fused kernel: grid = 136 pairs, 256 threads, 1 CTA/SM (SMEM ~207KB).
// ============================================================================
__global__ __launch_bounds__(256, 1)
void fused_kernel(const float* __restrict__ x,
                  const float* __restrict__ nItem,
                  const float* __restrict__ W2,
                  float* __restrict__ out)
{
    extern __shared__ uint32_t sm[];
    uint32_t* xA = sm + OFF_XA;          // [256][XSTR] fp16x2 words
    uint32_t* xB = sm + OFF_XB;          // [256][XSTR]
    uint32_t* w1 = sm + OFF_W1;          // [64][XSTR]
    uint32_t* Bs = sm + OFF_BS;          // [256][BSTR]
    float*   red = (float*)(sm + OFF_RED);

    const int tid  = threadIdx.x;
    const int wid  = tid >> 5;
    const int lane = tid & 31;
    const int r    = lane >> 2;
    const int c    = lane & 3;
    const int rowbase = wid * 32;

    // pair -> (ii <= jj)
    int q = blockIdx.x, jj = 0;
    while (q >= jj + 1) { q -= (jj + 1); ++jj; }
    const int ii = q;

    const uint32_t w1_base = smem_u32(w1);
    auto stage_w1 = [&](int h) {
        const char* src = (const char*)(g_W1h + (size_t)h * DHEAD * DIN);
        #pragma unroll
        for (int it = 0; it < 4; ++it) {
            int idx = tid + it * 256;
            int e = idx >> 4, dq = idx & 15;           // 16 uint4 per 128-half row
            cp_async16(w1_base + (e * XSTR + dq * 4) * 4, src + idx * 16);
        }
        cp_commit();
    };

    // ---- prologue: stage W1[0]; stage xA, xB (fp32 -> fp16) ----
    stage_w1(0);
    {
        const float4* gA = (const float4*)(x + (size_t)(jj * NSET + ii) * MITEM * DIN);
        const float4* gB = (const float4*)(x + (size_t)(ii * NSET + jj) * MITEM * DIN);
        #pragma unroll 4
        for (int it = 0; it < 32; ++it) {
            int idx = tid + it * 256;
            int row = idx >> 5, fq = idx & 31;
            float4 va = gA[idx];
            float4 vb = gB[idx];
            uint2 wa = { packh2(va.x, va.y), packh2(va.z, va.w) };
            uint2 wb = { packh2(vb.x, vb.y), packh2(vb.z, vb.w) };
            *(uint2*)&xA[row * XSTR + 2 * fq] = wa;
            *(uint2*)&xB[row * XSTR + 2 * fq] = wb;
        }
    }
    cp_wait0();
    __syncthreads();

    float stot = 0.f;

    #pragma unroll 1
    for (int h = 0; h < NHEAD; ++h) {
        uint32_t aF[2][4][4];          // score A operand (held in regs)

        // ================= projection of A then B =================
        #pragma unroll 1
        for (int pass = 0; pass < 2; ++pass) {
            const uint32_t* xs = pass ? xB : xA;
            float acc[2][8][4];        // [mt][n8-tile][4]
            #pragma unroll
            for (int mt = 0; mt < 2; ++mt)
                #pragma unroll
                for (int nt = 0; nt < 8; ++nt)
                    #pragma unroll
                    for (int e = 0; e < 4; ++e) acc[mt][nt][e] = 0.f;

            #pragma unroll
            for (int ks = 0; ks < 8; ++ks) {
                uint32_t aX[2][4];
                #pragma unroll
                for (int mt = 0; mt < 2; ++mt) {
                    uint2 lo = *(const uint2*)&xs[(rowbase + mt * 16 + r) * XSTR + ks * 8 + 2 * c];
                    uint2 hi = *(const uint2*)&xs[(rowbase + mt * 16 + r + 8) * XSTR + ks * 8 + 2 * c];
                    aX[mt][0] = lo.x; aX[mt][2] = lo.y;
                    aX[mt][1] = hi.x; aX[mt][3] = hi.y;
                }
                #pragma unroll
                for (int nt = 0; nt < 8; ++nt) {
                    uint2 b = *(const uint2*)&w1[(nt * 8 + r) * XSTR + ks * 8 + 2 * c];
                    mma_f16(acc[0][nt], aX[0], (const uint32_t*)&b);
                    mma_f16(acc[1][nt], aX[1], (const uint32_t*)&b);
                }
            }

            if (pass == 0) {
                // acc -> score A regs (direct layout correspondence)
                #pragma unroll
                for (int mt = 0; mt < 2; ++mt)
                    #pragma unroll
                    for (int k = 0; k < 4; ++k) {
                        aF[mt][k][0] = packh2(acc[mt][2 * k][0],     acc[mt][2 * k][1]);
                        aF[mt][k][1] = packh2(acc[mt][2 * k][2],     acc[mt][2 * k][3]);
                        aF[mt][k][2] = packh2(acc[mt][2 * k + 1][0], acc[mt][2 * k + 1][1]);
                        aF[mt][k][3] = packh2(acc[mt][2 * k + 1][2], acc[mt][2 * k + 1][3]);
                    }
            } else {
                // acc -> Bs SMEM (score B operand), conflict-free STS.64
                #pragma unroll
                for (int mt = 0; mt < 2; ++mt)
                    #pragma unroll
                    for (int k = 0; k < 4; ++k) {
                        uint2 lo = { packh2(acc[mt][2 * k][0],     acc[mt][2 * k][1]),
                                     packh2(acc[mt][2 * k + 1][0], acc[mt][2 * k + 1][1]) };
                        uint2 hi = { packh2(acc[mt][2 * k][2],     acc[mt][2 * k][3]),
                                     packh2(acc[mt][2 * k + 1][2], acc[mt][2 * k + 1][3]) };
                        *(uint2*)&Bs[(rowbase + mt * 16 + r) * BSTR + k * 8 + 2 * c]     = lo;
                        *(uint2*)&Bs[(rowbase + mt * 16 + r + 8) * BSTR + k * 8 + 2 * c] = hi;
                    }
            }
        }

        __syncthreads();                 // Bs published; W1[h] reads done
        if (h < NHEAD - 1) stage_w1(h + 1);   // prefetch overlaps score

        // ================= score =================
        float s1a = 0.f, s1b = 0.f, s2a = 0.f, s2b = 0.f;
        #pragma unroll 1
        for (int nt = 0; nt < 32; ++nt) {
            float acc0[4] = {0.f, 0.f, 0.f, 0.f};
            float acc1[4] = {0.f, 0.f, 0.f, 0.f};
            #pragma unroll
            for (int k = 0; k < 4; ++k) {
                uint2 b = *(const uint2*)&Bs[(nt * 8 + r) * BSTR + k * 8 + 2 * c];
                mma_f16(acc0, aF[0][k], (const uint32_t*)&b);
                mma_f16(acc1, aF[1][k], (const uint32_t*)&b);
            }
            #pragma unroll
            for (int e = 0; e < 4; ++e) {
                s1a += acc0[e];  s2a += fabsf(acc0[e]);
                s1b += acc1[e];  s2b += fabsf(acc1[e]);
            }
        }
        stot += W2[h] * (0.65f * (s1a + s1b) + 0.35f * (s2a + s2b));

        if (h < NHEAD - 1) cp_wait0();   // W1[h+1] landed
        __syncthreads();                 // Bs reads done; W1[h+1] visible
    }

    // ---- CTA reduce + write both symmetric outputs ----
    #pragma unroll
    for (int off = 16; off; off >>= 1)
        stot += __shfl_xor_sync(0xffffffffu, stot, off);
    if (lane == 0) red[wid] = stot;
    __syncthreads();
    if (tid == 0) {
        float s = 0.f;
        #pragma unroll
        for (int w = 0; w < 8; ++w) s += red[w];
        float v = s / (8.0f * nItem[ii] * nItem[jj]);   // 8 = sqrt(D=64)
        out[jj * NSET + ii] = v;
        out[ii * NSET + jj] = v;
    }
}

// ---------------- entry point ----------------
extern "C" void kernel_launch(void* const* d_in, const int* in_sizes, int n_in,
                              void* d_out, int out_size)
{
    const float* x = nullptr;
    const float* nItem = nullptr;
    const float* W1 = nullptr;
    const float* W2 = nullptr;
    for (int k = 0; k < n_in; ++k) {
        switch (in_sizes[k]) {
            case NSET * NSET * MITEM * DIN: x     = (const float*)d_in[k]; break;
            case NSET:                      nItem = (const float*)d_in[k]; break;
            case DIN * NHEAD * DHEAD:       W1    = (const float*)d_in[k]; break;
            case NHEAD:                     W2    = (const float*)d_in[k]; break;
        }
    }

    static bool attr_done = false;
    if (!attr_done) {
        cudaFuncSetAttribute(fused_kernel,
                             cudaFuncAttributeMaxDynamicSharedMemorySize, SMEM_BYTES);
        attr_done = true;
    }

    prep_w1<<<64, 1024>>>(W1);
    fused_kernel<<<NPAIR, 256, SMEM_BYTES>>>(x, nItem, W2, (float*)d_out);
}